// round 5
// baseline (speedup 1.0000x reference)
#include <cuda_runtime.h>
#include <cstdint>

// out[b, c*12+i, h, (w'+1)%112] = sum_{k,j} w1[i,k,j] * y[(h+k-4), w', j]
//   y row m valid iff -1 <= m <= 110 (m == -1 wraps to x row 111), else 0
// y[m, w', j] = sum_{j0} x[b, c*12+j0, m%112, w'] * w2[j0, j]
//
// w-roll folded into the OUTPUT store; h-roll + conv gating folded into
// stage-1 row selection/zeroing. All math packed fp32x2. Weights in SMEM,
// duplicated-lane f32x2, fetched via LDS.128 to halve crossbar wavefronts.

#define HH 112
#define WW 112
#define TILE_H 8
#define YROWS 14          // TILE_H + 6 halo
#define NJ 12
#define NI 9
#define NO 12
#define THREADS 224

typedef unsigned long long u64;

__device__ __forceinline__ u64 fma2(u64 a, u64 b, u64 c) {
    u64 d;
    asm("fma.rn.f32x2 %0, %1, %2, %3;" : "=l"(d) : "l"(a), "l"(b), "l"(c));
    return d;
}
__device__ __forceinline__ u64 pack2(float lo, float hi) {
    u64 d;
    asm("mov.b64 %0, {%1, %2};" : "=l"(d) : "f"(lo), "f"(hi));
    return d;
}
__device__ __forceinline__ void unpack2(u64 v, float& lo, float& hi) {
    asm("mov.b64 {%0, %1}, %2;" : "=f"(lo), "=f"(hi) : "l"(v));
}

// dynamic smem:
//   u64  w1d[756] : w1 repacked [j][k][i] (dup f32x2), k-contiguous per j, 16B aligned
//   u64  w2d[144] : w2 [j0][i] padded to 12/row (dup f32x2), 16B-aligned rows
//   float ysm[YROWS][NI][WW]
#define SMEM_W1D_ELEMS 756
#define SMEM_W2D_ELEMS 144
#define SMEM_Y_OFF ((SMEM_W1D_ELEMS + SMEM_W2D_ELEMS) * 8)
#define SMEM_TOTAL (SMEM_Y_OFF + YROWS * NI * WW * 4)

__global__ void __launch_bounds__(THREADS, 3)
fused_shiftconv_kernel(const float* __restrict__ x,
                       const float* __restrict__ w1,
                       const float* __restrict__ w2,
                       float* __restrict__ out)
{
    extern __shared__ char smem[];
    u64* w1d = reinterpret_cast<u64*>(smem);
    u64* w2d = w1d + SMEM_W1D_ELEMS;
    float* ysm = reinterpret_cast<float*>(smem + SMEM_Y_OFF);

    const int tid = threadIdx.x;
    const int h0  = blockIdx.x * TILE_H;   // 14 tiles
    const int c   = blockIdx.y;            // 2 groups
    const int b   = blockIdx.z;            // 128 batches

    // ---- weight repack ----
    for (int idx = tid; idx < SMEM_W1D_ELEMS; idx += THREADS) {
        // src w1 layout [i][k][j]: idx = i*63 + k*9 + j
        int i = idx / 63;
        int rem = idx - i * 63;
        int k = rem / 9;
        int j = rem - k * 9;
        float v = w1[idx];
        w1d[(j * 7 + k) * 12 + i] = pack2(v, v);   // dst [j][k][i]
    }
    for (int idx = tid; idx < 108; idx += THREADS) {
        int j0 = idx / 9;
        int i  = idx - j0 * 9;
        float v = w2[idx];
        w2d[j0 * 12 + i] = pack2(v, v);
    }
    __syncthreads();

    const float* xb = x + (size_t)(b * 24 + c * 12) * (HH * WW);

    // ---- stage 1: y[l][i][w'] = sum_j0 x[j0, (h0+l-4)%112, w'] * w2[j0][i]
    for (int g = tid; g < YROWS * 28; g += THREADS) {
        int l  = g / 28;
        int wq = g - l * 28;
        int m  = h0 + l - 4;
        float* ybase = ysm + (l * NI) * WW + (wq << 2);
        if (m >= -1 && m <= 110) {
            int xr = (m < 0) ? (m + HH) : m;   // only m == -1 wraps (row 111)
            const float4* xrow = reinterpret_cast<const float4*>(
                xb + (size_t)xr * WW + (wq << 2));
            u64 acc[2][NI];
            #pragma unroll
            for (int v = 0; v < 2; ++v)
                #pragma unroll
                for (int i = 0; i < NI; ++i) acc[v][i] = 0ULL;

            #pragma unroll 4
            for (int j0 = 0; j0 < NJ; ++j0) {
                float4 xv = __ldg(xrow + (size_t)j0 * (HH * WW / 4));
                u64 xq0 = pack2(xv.x, xv.y);
                u64 xq1 = pack2(xv.z, xv.w);
                const ulonglong2* wrv =
                    reinterpret_cast<const ulonglong2*>(w2d + j0 * 12);
                ulonglong2 p0 = wrv[0], p1 = wrv[1], p2 = wrv[2], p3 = wrv[3];
                u64 wv[NI];
                wv[0] = p0.x; wv[1] = p0.y; wv[2] = p1.x; wv[3] = p1.y;
                wv[4] = p2.x; wv[5] = p2.y; wv[6] = p3.x; wv[7] = p3.y;
                wv[8] = w2d[j0 * 12 + 8];
                #pragma unroll
                for (int i = 0; i < NI; ++i) {
                    acc[0][i] = fma2(xq0, wv[i], acc[0][i]);
                    acc[1][i] = fma2(xq1, wv[i], acc[1][i]);
                }
            }
            #pragma unroll
            for (int i = 0; i < NI; ++i) {
                *reinterpret_cast<u64*>(ybase + i * WW)     = acc[0][i];
                *reinterpret_cast<u64*>(ybase + i * WW + 2) = acc[1][i];
            }
        } else {
            #pragma unroll
            for (int i = 0; i < NI; ++i) {
                *reinterpret_cast<u64*>(ybase + i * WW)     = 0ULL;
                *reinterpret_cast<u64*>(ybase + i * WW + 2) = 0ULL;
            }
        }
    }
    __syncthreads();

    // ---- stage 2: 7-tap conv over rows, 9 -> 12 channels, f32x2 ----
    {
        const int u  = tid % 56;          // y w-pair (cols 2u, 2u+1)
        const int rb = tid / 56;          // 0..3
        const int hl = rb * 2;            // 2 output rows per thread
        u64 acc[2][NO];
        #pragma unroll
        for (int r = 0; r < 2; ++r)
            #pragma unroll
            for (int i = 0; i < NO; ++i) acc[r][i] = 0ULL;

        const float* ycol = ysm + 2 * u;
        #pragma unroll 1
        for (int j = 0; j < NI; ++j) {
            u64 yw[8];                    // y rows hl .. hl+7, channel j
            #pragma unroll
            for (int t = 0; t < 8; ++t)
                yw[t] = *reinterpret_cast<const u64*>(ycol + ((hl + t) * NI + j) * WW);
            const ulonglong2* wp =
                reinterpret_cast<const ulonglong2*>(w1d + j * 84); // [j][k][i]
            #pragma unroll
            for (int k = 0; k < 7; ++k) {
                const ulonglong2* wk = wp + k * 6;
                #pragma unroll
                for (int t = 0; t < 6; ++t) {
                    ulonglong2 wpair = wk[t];
                    acc[0][2 * t]     = fma2(yw[k],     wpair.x, acc[0][2 * t]);
                    acc[1][2 * t]     = fma2(yw[k + 1], wpair.x, acc[1][2 * t]);
                    acc[0][2 * t + 1] = fma2(yw[k],     wpair.y, acc[0][2 * t + 1]);
                    acc[1][2 * t + 1] = fma2(yw[k + 1], wpair.y, acc[1][2 * t + 1]);
                }
            }
        }

        // output columns: w-roll by +1 -> out cols (2u+1) and (2u+2)%112
        const int colA = 2 * u + 1;
        const int colB = (2 * u + 2 == WW) ? 0 : 2 * u + 2;
        float* ob = out + ((size_t)(b * 24 + c * 12) * HH + (h0 + hl)) * WW;
        #pragma unroll
        for (int i = 0; i < NO; ++i) {
            float* orow = ob + (size_t)i * (HH * WW);
            #pragma unroll
            for (int r = 0; r < 2; ++r) {
                float lo, hi;
                unpack2(acc[r][i], lo, hi);
                orow[r * WW + colA] = lo;
                orow[r * WW + colB] = hi;
            }
        }
    }
}

extern "C" void kernel_launch(void* const* d_in, const int* in_sizes, int n_in,
                              void* d_out, int out_size)
{
    (void)in_sizes; (void)n_in; (void)out_size;
    const float* x  = (const float*)d_in[0];
    const float* w1 = (const float*)d_in[1];
    const float* w2 = (const float*)d_in[2];
    float* out = (float*)d_out;

    cudaFuncSetAttribute(fused_shiftconv_kernel,
                         cudaFuncAttributeMaxDynamicSharedMemorySize, SMEM_TOTAL);
    dim3 grid(HH / TILE_H, 2, 128);
    fused_shiftconv_kernel<<<grid, THREADS, SMEM_TOTAL>>>(x, w1, w2, out);
}